// round 9
// baseline (speedup 1.0000x reference)
#include <cuda_runtime.h>
#include <cuda_bf16.h>
#include <cstdint>

#define B_TOT 8192
#define T_STEPS 90
#define H 128
#define NB 64
#define NCTA 128
#define NTHR 512
#define SKB 272u          // act row stride bytes (136 bf16); 32 rows/buffer = 8704 B
#define LOB 8704u         // lo-part offset within an act buffer pair
#define CSTRIDE 36        // c buffer row stride (floats), 32 cols + 4 pad

// ---- SMEM byte offsets (gang-parametrized) ----
#define GXA(g)   ((uint32_t)(g) * 17408u)                 // [hi 8704][lo 8704]
#define GH0(g)   (34816u + (uint32_t)(g) * 17408u)
#define GH1(g)   (69632u + (uint32_t)(g) * 17408u)
#define GC0(g)   (104448u + (uint32_t)(g) * 18432u)       // [128][36] f32
#define GC1(g)   (141312u + (uint32_t)(g) * 18432u)
#define GSCR(g)  (178176u + (uint32_t)(g) * 16896u)       // [32][132] f32 proj scratch
#define GLNS(g)  (211968u + (uint32_t)(g) * 1024u)        // LN partials/mu/rs
#define GXROW(g) (214016u + (uint32_t)(g) * 1024u)        // [32][8] f32
#define OFF_WIN  216064u                                   // [128][8] f32 (slot7=b_in)
#define OFF_LNP  220160u                                   // g_in,be_in,g_ln,be_ln
#define OFF_B0   222208u
#define OFF_B1   224256u
#define SMEM_TOTAL 226304u
// tail overlays: scr f32 [128][65] @0 (XA dead), d1o @34816 (H0 dead), d2o @69632 (H1 dead post-LN)

// ---- device globals ----
// layout: [(L*8+w)][g][ks][hl][512B]  (strides 65536 / 16384 / 1024 / 512)
__device__ __align__(256) uint8_t g_Wpack[1048576];
__device__ float g_Wd1t[128 * 128];
__device__ float g_Wd2t[128 * 64];
__device__ float g_bias0[512];
__device__ float g_bias1[512];

__global__ void prep_kernel(const float* __restrict__ Wih0, const float* __restrict__ Whh0,
                            const float* __restrict__ bih0, const float* __restrict__ bhh0,
                            const float* __restrict__ Wih1, const float* __restrict__ Whh1,
                            const float* __restrict__ bih1, const float* __restrict__ bhh1,
                            const float* __restrict__ Wd1,  const float* __restrict__ Wd2)
{
    int idx = blockIdx.x * blockDim.x + threadIdx.x;
    int stride = gridDim.x * blockDim.x;
    for (int i = idx; i < 524288; i += stride) {
        int e    = i & 1;
        int reg  = (i >> 1) & 3;
        int lane = (i >> 3) & 31;
        int hl   = (i >> 8) & 1;
        int ks   = (i >> 9) & 15;
        int g    = (i >> 13) & 3;
        int w    = (i >> 15) & 7;
        int L    = (i >> 18) & 1;
        int j = g * 128 + w * 16 + (lane >> 2) + (reg & 1) * 8;
        int k = ks * 16 + (lane & 3) * 2 + ((reg >> 1) & 1) * 8 + e;
        float v;
        if (L == 0) v = (k < H) ? Wih0[j * H + k] : Whh0[j * H + (k - H)];
        else        v = (k < H) ? Wih1[j * H + k] : Whh1[j * H + (k - H)];
        __nv_bfloat16 hi = __float2bfloat16(v);
        __nv_bfloat16 res = __float2bfloat16(v - __bfloat162float(hi));
        reinterpret_cast<__nv_bfloat16*>(g_Wpack)[i] = hl ? res : hi;
    }
    for (int i = idx; i < 128 * 128; i += stride) {
        int k = i >> 7, d = i & 127;
        g_Wd1t[i] = Wd1[d * H + k];
    }
    for (int i = idx; i < 128 * 64; i += stride) {
        int k = i >> 6, d = i & 63;
        g_Wd2t[i] = Wd2[d * 128 + k];
    }
    for (int i = idx; i < 512; i += stride) {
        g_bias0[i] = bih0[i] + bhh0[i];
        g_bias1[i] = bih1[i] + bhh1[i];
    }
}

// ---- helpers ----
__device__ __forceinline__ uint32_t smem_u32_of(const void* p) {
    uint32_t a;
    asm("{ .reg .u64 t; cvta.to.shared.u64 t, %1; cvt.u32.u64 %0, t; }" : "=r"(a) : "l"(p));
    return a;
}
__device__ __forceinline__ void gbar(int id) {
    asm volatile("bar.sync %0, 256;" :: "r"(id) : "memory");
}
__device__ __forceinline__ void ldmx4(uint32_t& r0, uint32_t& r1, uint32_t& r2, uint32_t& r3,
                                      uint32_t addr) {
    asm volatile("ldmatrix.sync.aligned.m8n8.x4.shared.b16 {%0,%1,%2,%3}, [%4];"
                 : "=r"(r0), "=r"(r1), "=r"(r2), "=r"(r3) : "r"(addr));
}
__device__ __forceinline__ void mma16816(float* c, uint4 a, uint32_t b0, uint32_t b1) {
    asm volatile("mma.sync.aligned.m16n8k16.row.col.f32.bf16.bf16.f32 "
                 "{%0,%1,%2,%3}, {%4,%5,%6,%7}, {%8,%9}, {%0,%1,%2,%3};"
                 : "+f"(c[0]), "+f"(c[1]), "+f"(c[2]), "+f"(c[3])
                 : "r"(a.x), "r"(a.y), "r"(a.z), "r"(a.w), "r"(b0), "r"(b1));
}
__device__ __forceinline__ float sigf(float x) {
    return __fdividef(1.f, 1.f + __expf(-x));
}
__device__ __forceinline__ float tanh_fast(float x) {
    return 2.f * sigf(2.f * x) - 1.f;
}
__device__ __forceinline__ void store_hilo(uint8_t* smb, uint32_t off_hi,
                                           uint32_t byte, float v) {
    __nv_bfloat16 hi = __float2bfloat16(v);
    __nv_bfloat16 lo = __float2bfloat16(v - __bfloat162float(hi));
    *reinterpret_cast<__nv_bfloat16*>(smb + off_hi + byte) = hi;
    *reinterpret_cast<__nv_bfloat16*>(smb + off_hi + LOB + byte) = lo;
}

__global__ void __launch_bounds__(NTHR, 1)
lstm_hmma_kernel(const float* __restrict__ x,
                 const float* __restrict__ W_in, const float* __restrict__ b_in,
                 const float* __restrict__ g_in, const float* __restrict__ be_in,
                 const float* __restrict__ g_ln, const float* __restrict__ be_ln,
                 const float* __restrict__ b_d1, const float* __restrict__ b_d2,
                 const float* __restrict__ W_d3, const float* __restrict__ b_d3,
                 float* __restrict__ out)
{
    extern __shared__ __align__(256) uint8_t smb[];
    const int tid  = threadIdx.x;
    const int w    = tid >> 5;
    const int wq   = w & 7;            // h-row group within gang
    const int gang = w >> 3;           // 0: rows 0-31, 1: rows 32-63
    const int gt   = tid & 255;        // thread id within gang
    const int lane = tid & 31;
    const int bbase = blockIdx.x * NB;
    const int barid = gang + 1;

    uint32_t smbase = smem_u32_of(smb);
    float* wins  = reinterpret_cast<float*>(smb + OFF_WIN);
    float* lnp   = reinterpret_cast<float*>(smb + OFF_LNP);
    float* b0s   = reinterpret_cast<float*>(smb + OFF_B0);
    float* b1s   = reinterpret_cast<float*>(smb + OFF_B1);
    float* scrg  = reinterpret_cast<float*>(smb + GSCR(gang));
    float* lns   = reinterpret_cast<float*>(smb + GLNS(gang));
    float* xrowg = reinterpret_cast<float*>(smb + GXROW(gang));

    // ---- prologue (full CTA) ----
    for (int i = tid; i < 104448 / 4; i += NTHR)
        reinterpret_cast<uint32_t*>(smb)[i] = 0u;                        // act buffers
    for (int i = tid; i < (178176 - 104448) / 4; i += NTHR)
        reinterpret_cast<float*>(smb + 104448)[i] = 0.f;                 // c buffers
    for (int i = tid; i < H * 7; i += NTHR) {
        int h = i / 7, f = i % 7;
        wins[h * 8 + f] = W_in[i];
    }
    for (int i = tid; i < H; i += NTHR) {
        wins[i * 8 + 7] = b_in[i];
        lnp[i] = g_in[i]; lnp[128 + i] = be_in[i];
        lnp[256 + i] = g_ln[i]; lnp[384 + i] = be_ln[i];
    }
    for (int i = tid; i < 512; i += NTHR) { b0s[i] = g_bias0[i]; b1s[i] = g_bias1[i]; }
    __syncthreads();

    // ldmatrix lane offset within a 16-row (2 n-tile) group
    const int tI = lane >> 3, r = lane & 7;
    const uint32_t loffb = (uint32_t)((tI >> 1) * 8 + r) * SKB + (uint32_t)(tI & 1) * 16u;

    const int m0  = wq * 16 + (lane >> 2);     // h row (second row = +8)
    const int nb0 = (lane & 3) * 2;

    for (int t = 0; t < T_STEPS; ++t) {
        // ======== phase A (gang-local): x -> proj -> LN -> bf16 hi/lo xa ========
        if (gt < 32) {
            const float* xr = x + ((long long)(bbase + gang * 32 + gt) * T_STEPS + t) * 7;
#pragma unroll
            for (int f = 0; f < 7; ++f) xrowg[gt * 8 + f] = xr[f];
        }
        gbar(barid);
        {
            int b = gt >> 3, hq = gt & 7;
            float xv[7];
#pragma unroll
            for (int f = 0; f < 7; ++f) xv[f] = xrowg[b * 8 + f];
            for (int h = hq * 16; h < hq * 16 + 16; ++h) {
                float s = wins[h * 8 + 7];
#pragma unroll
                for (int f = 0; f < 7; ++f) s += wins[h * 8 + f] * xv[f];
                scrg[b * 132 + h] = s;
            }
        }
        gbar(barid);
        if (gt < 64) {
            int b = gt >> 1, hf = gt & 1;
            float s = 0.f, ss = 0.f;
            for (int h = hf * 64; h < hf * 64 + 64; ++h) {
                float v = scrg[b * 132 + h];
                s += v; ss += v * v;
            }
            lns[b * 2 + hf] = s;
            lns[64 + b * 2 + hf] = ss;
        }
        gbar(barid);
        if (gt < 32) {
            int b = gt;
            float s  = lns[b * 2] + lns[b * 2 + 1];
            float ss = lns[64 + b * 2] + lns[64 + b * 2 + 1];
            float mu = s * (1.f / H);
            float rs = rsqrtf(ss * (1.f / H) - mu * mu + 1e-5f);
            lns[128 + b] = mu;
            lns[160 + b] = rs;
        }
        gbar(barid);
        for (int i = gt; i < 32 * H; i += 256) {
            int b = i >> 7, h = i & 127;
            float v = (scrg[b * 132 + h] - lns[128 + b]) * lns[160 + b] * lnp[h] + lnp[128 + h];
            store_hilo(smb, GXA(gang), (uint32_t)b * SKB + (uint32_t)h * 2u, v);
        }
        gbar(barid);

        // ======== two LSTM layers (gang-local) ========
#pragma unroll 1
        for (int L = 0; L < 2; ++L) {
            const uint8_t* wbase = g_Wpack + (size_t)(L * 8 + wq) * 65536;
            uint32_t in_hi  = smbase + (L == 0 ? GXA(gang) : GH0(gang));
            uint32_t re_hi  = smbase + (L == 0 ? GH0(gang) : GH1(gang));
            uint32_t out_hi = (L == 0 ? GH0(gang) : GH1(gang));
            float* cbuf = reinterpret_cast<float*>(smb + (L == 0 ? GC0(gang) : GC1(gang)));
            const float* bs = (L == 0) ? b0s : b1s;

            float acc[4][4][4];
#pragma unroll
            for (int g = 0; g < 4; ++g)
#pragma unroll
                for (int nt = 0; nt < 4; ++nt)
#pragma unroll
                    for (int q = 0; q < 4; ++q) acc[g][nt][q] = 0.f;

#pragma unroll 2
            for (int ks = 0; ks < 16; ++ks) {
                uint32_t bh_base = ((ks < 8) ? in_hi : re_hi) + (uint32_t)(ks & 7) * 32u + loffb;
                uint32_t bh[8], bl[8];
#pragma unroll
                for (int tp = 0; tp < 2; ++tp) {
                    ldmx4(bh[tp * 4], bh[tp * 4 + 1], bh[tp * 4 + 2], bh[tp * 4 + 3],
                          bh_base + (uint32_t)tp * 16u * SKB);
                    ldmx4(bl[tp * 4], bl[tp * 4 + 1], bl[tp * 4 + 2], bl[tp * 4 + 3],
                          bh_base + LOB + (uint32_t)tp * 16u * SKB);
                }
                const uint8_t* wk = wbase + ks * 1024 + lane * 16;
#pragma unroll
                for (int g = 0; g < 4; ++g) {
                    uint4 ahi = *reinterpret_cast<const uint4*>(wk + g * 16384);
                    uint4 alo = *reinterpret_cast<const uint4*>(wk + g * 16384 + 512);
#pragma unroll
                    for (int nt = 0; nt < 4; ++nt) {
                        mma16816(acc[g][nt], ahi, bh[nt * 2], bh[nt * 2 + 1]);
                        mma16816(acc[g][nt], alo, bh[nt * 2], bh[nt * 2 + 1]);
                        mma16816(acc[g][nt], ahi, bl[nt * 2], bl[nt * 2 + 1]);
                    }
                }
            }
            gbar(barid);   // all reads of rec buffers done before writes

            // ---- pointwise ----
            float bI[2] = { bs[m0],       bs[m0 + 8] };
            float bF[2] = { bs[128 + m0], bs[128 + m0 + 8] };
            float bG[2] = { bs[256 + m0], bs[256 + m0 + 8] };
            float bO[2] = { bs[384 + m0], bs[384 + m0 + 8] };
#pragma unroll
            for (int nt = 0; nt < 4; ++nt) {
#pragma unroll
                for (int mi = 0; mi < 2; ++mi) {
                    int h = m0 + mi * 8;
#pragma unroll
                    for (int e = 0; e < 2; ++e) {
                        int n = nt * 8 + nb0 + e;
                        float pi = acc[0][nt][mi * 2 + e] + bI[mi];
                        float pf = acc[1][nt][mi * 2 + e] + bF[mi];
                        float pg = acc[2][nt][mi * 2 + e] + bG[mi];
                        float po = acc[3][nt][mi * 2 + e] + bO[mi];
                        float cp = cbuf[h * CSTRIDE + n];
                        float cn = sigf(pf) * cp + sigf(pi) * tanh_fast(pg);
                        cbuf[h * CSTRIDE + n] = cn;
                        float hv = sigf(po) * tanh_fast(cn);
                        store_hilo(smb, out_hi, (uint32_t)n * SKB + (uint32_t)h * 2u, hv);
                    }
                }
            }
            gbar(barid);
        }
    }

    // ================= tail (full CTA) =================
    __syncthreads();
    float* scr = reinterpret_cast<float*>(smb);            // overlays XA (dead)

    if (tid < NB) {
        int b = tid, gg = b >> 5, n = b & 31;
        uint32_t base = GH1(gg) + (uint32_t)n * SKB;
        float s = 0.f, ss = 0.f;
        float hv[H];
        for (int h = 0; h < H; ++h) {
            float vh = __bfloat162float(
                *reinterpret_cast<__nv_bfloat16*>(smb + base + h * 2));
            float vl = __bfloat162float(
                *reinterpret_cast<__nv_bfloat16*>(smb + base + LOB + h * 2));
            float v = vh + vl;
            hv[h] = v;
            s += v; ss += v * v;
        }
        float mu = s * (1.f / H);
        float rs = rsqrtf(ss * (1.f / H) - mu * mu + 1e-5f);
        for (int h = 0; h < H; ++h)
            scr[h * 65 + b] = (hv[h] - mu) * rs * lnp[256 + h] + lnp[384 + h];
    }
    __syncthreads();

    float* d1o = reinterpret_cast<float*>(smb + 34816u);   // overlays H0 (dead)
    float* d2o = reinterpret_cast<float*>(smb + 69632u);   // overlays H1 (dead)

    // dense1
    if (tid < 256) {
        int d4 = (tid >> 3) * 4, bb = (tid & 7) * 8;
        float a[4][8];
#pragma unroll
        for (int d = 0; d < 4; ++d)
#pragma unroll
            for (int b = 0; b < 8; ++b) a[d][b] = 0.f;
        for (int k = 0; k < H; ++k) {
            float4 wv = *reinterpret_cast<const float4*>(&g_Wd1t[k * 128 + d4]);
            float av[8];
#pragma unroll
            for (int b = 0; b < 8; ++b) av[b] = scr[k * 65 + bb + b];
#pragma unroll
            for (int b = 0; b < 8; ++b) {
                a[0][b] += wv.x * av[b]; a[1][b] += wv.y * av[b];
                a[2][b] += wv.z * av[b]; a[3][b] += wv.w * av[b];
            }
        }
#pragma unroll
        for (int d = 0; d < 4; ++d) {
            float bd = b_d1[d4 + d];
#pragma unroll
            for (int b = 0; b < 8; ++b) {
                float v = a[d][b] + bd;
                d1o[(d4 + d) * 64 + bb + b] = v > 0.f ? v : 0.f;
            }
        }
    }
    __syncthreads();

    // dense2
    if (tid < 256) {
        int d4 = (tid >> 4) * 4, bb = (tid & 15) * 4;
        float a[4][4];
#pragma unroll
        for (int d = 0; d < 4; ++d)
#pragma unroll
            for (int b = 0; b < 4; ++b) a[d][b] = 0.f;
        for (int k = 0; k < 128; ++k) {
            float4 wv = *reinterpret_cast<const float4*>(&g_Wd2t[k * 64 + d4]);
            float av[4];
#pragma unroll
            for (int b = 0; b < 4; ++b) av[b] = d1o[k * 64 + bb + b];
#pragma unroll
            for (int b = 0; b < 4; ++b) {
                a[0][b] += wv.x * av[b]; a[1][b] += wv.y * av[b];
                a[2][b] += wv.z * av[b]; a[3][b] += wv.w * av[b];
            }
        }
#pragma unroll
        for (int d = 0; d < 4; ++d) {
            float bd = b_d2[d4 + d];
#pragma unroll
            for (int b = 0; b < 4; ++b) {
                float v = a[d][b] + bd;
                d2o[(d4 + d) * 64 + bb + b] = v > 0.f ? v : 0.f;
            }
        }
    }
    __syncthreads();

    // dense3
    if (tid < 240) {
        int d = tid % 30, bq = (tid / 30) * 8;
        float a[8];
#pragma unroll
        for (int b = 0; b < 8; ++b) a[b] = 0.f;
        for (int k = 0; k < 64; ++k) {
            float wv = W_d3[d * 64 + k];
#pragma unroll
            for (int b = 0; b < 8; ++b) a[b] += wv * d2o[k * 64 + bq + b];
        }
        float bd = b_d3[d];
#pragma unroll
        for (int b = 0; b < 8; ++b)
            out[(long long)(bbase + bq + b) * 30 + d] = a[b] + bd;
    }
}

// ---------------------------------------------------------------------------
extern "C" void kernel_launch(void* const* d_in, const int* in_sizes, int n_in,
                              void* d_out, int out_size)
{
    const float* x     = (const float*)d_in[0];
    const float* W_in  = (const float*)d_in[1];
    const float* b_in  = (const float*)d_in[2];
    const float* g_in  = (const float*)d_in[3];
    const float* be_in = (const float*)d_in[4];
    const float* Wih0  = (const float*)d_in[5];
    const float* Whh0  = (const float*)d_in[6];
    const float* bih0  = (const float*)d_in[7];
    const float* bhh0  = (const float*)d_in[8];
    const float* Wih1  = (const float*)d_in[9];
    const float* Whh1  = (const float*)d_in[10];
    const float* bih1  = (const float*)d_in[11];
    const float* bhh1  = (const float*)d_in[12];
    const float* g_ln  = (const float*)d_in[13];
    const float* be_ln = (const float*)d_in[14];
    const float* W_d1  = (const float*)d_in[15];
    const float* b_d1  = (const float*)d_in[16];
    const float* W_d2  = (const float*)d_in[17];
    const float* b_d2  = (const float*)d_in[18];
    const float* W_d3  = (const float*)d_in[19];
    const float* b_d3  = (const float*)d_in[20];
    float* out = (float*)d_out;

    prep_kernel<<<128, 256>>>(Wih0, Whh0, bih0, bhh0, Wih1, Whh1, bih1, bhh1,
                              W_d1, W_d2);

    cudaFuncSetAttribute(lstm_hmma_kernel,
                         cudaFuncAttributeMaxDynamicSharedMemorySize,
                         (int)SMEM_TOTAL);
    lstm_hmma_kernel<<<NCTA, NTHR, SMEM_TOTAL>>>(x, W_in, b_in, g_in, be_in,
                                                 g_ln, be_ln, b_d1, b_d2,
                                                 W_d3, b_d3, out);
}